// round 12
// baseline (speedup 1.0000x reference)
#include <cuda_runtime.h>
#include <cstdint>

// ---------------------------------------------------------------------------
// MoE_72808285602017 — PropertyLossTracker fused segment reduction
//   inputs : property_ids (N int32), token_losses (N f32),
//            prop_freq (P f32), batch_counter (1 int32)
//   outputs: [stratified_loss, unweighted_loss, new_freq[P]]  (P+2 f32)
//
// R12: hybrid atomic routing DONE RIGHT. R4 failed because 1/4 of tokens hit
//      4096 SHARED global addresses (L2 per-address serialization). Now each
//      worker CTA owns a private row g_part[cta][4096]: the 1-in-4 REDs spread
//      over 606k distinct addresses across all 184 LTS slices (contention-free
//      regime), running concurrently with the smem-ATOMS pipe that carries the
//      other 3/4. Epilogue merges the 148 partial rows (coalesced, L2-hot,
//      all-integer => deterministic) and re-zeroes them in-pass.
// ---------------------------------------------------------------------------

#define NPROP 4096
#define WORKERS 148                   // 1 CTA/SM

// Local 32-bit cell: (count << 24) + round(loss * 2^16) via one FFMA+F2I
// smem path carries 3/4 of ~113k tokens/CTA -> ~20.7 counts/cell (cap 255).
#define LSCALE 65536.0f
#define LBIAS  16777216.0f            // 2^24 == one count unit (32-bit cells)
#define LCNT_SHIFT 24

// Global 64-bit cell: (count << 40) + sum_units16
#define GCNT_SHIFT 40
#define GINV_SCALE (1.0f / 65536.0f)
#define GONE (1ULL << GCNT_SHIFT)

#define SCALE32 4294967296.0          // 2^32 fixed point for scalar merge

__device__ unsigned long long g_acc[NPROP];            // smem-path totals
__device__ unsigned int       g_part[WORKERS * NPROP]; // per-CTA direct-RED rows
__device__ unsigned long long g_scal[3];               // {mw, w, t_units16}
__device__ unsigned int       g_ticket;                // epilogue block ticket

// --- Kernel 1: token accumulation (3/4 smem ATOMS + 1/4 private-row REDG) ----
__global__ void __launch_bounds__(1024, 1)
segacc_kernel(const int* __restrict__ ids,
              const float* __restrict__ losses,
              long long n)
{
    // PDL: let the epilogue grid launch/prefetch/park early (harmless if not).
    cudaTriggerProgrammaticLaunchCompletion();

    __shared__ unsigned int s_acc[NPROP];
    #pragma unroll
    for (int i = threadIdx.x; i < NPROP; i += 1024) s_acc[i] = 0u;
    __syncthreads();

    unsigned int* myrow = &g_part[blockIdx.x * NPROP];  // CTA-private: no contention

    const long long n4 = n >> 2;                 // N is a multiple of 4
    const int4*   id4 = (const int4*)ids;
    const float4* ls4 = (const float4*)losses;
    const long long stride = (long long)gridDim.x * 1024;

    long long i = (long long)blockIdx.x * 1024 + threadIdx.x;
    #pragma unroll 2
    for (; i < n4; i += stride) {
        int4   id = id4[i];
        float4 ls = ls4[i];
        // 3/4 of tokens -> shared-memory atomic pipe
        atomicAdd(&s_acc[id.x], __float2uint_rn(fmaf(ls.x, LSCALE, LBIAS)));
        atomicAdd(&s_acc[id.y], __float2uint_rn(fmaf(ls.y, LSCALE, LBIAS)));
        atomicAdd(&s_acc[id.z], __float2uint_rn(fmaf(ls.z, LSCALE, LBIAS)));
        // 1/4 of tokens -> L2 atomic ALU, CTA-private row (RED, no return)
        atomicAdd(&myrow[id.w], __float2uint_rn(fmaf(ls.w, LSCALE, LBIAS)));
    }
    // scalar tail (defensive; N % 4 == 0 here)
    for (long long t = (n4 << 2) + (long long)blockIdx.x * 1024 + threadIdx.x;
         t < n; t += stride) {
        atomicAdd(&s_acc[ids[t]], __float2uint_rn(fmaf(losses[t], LSCALE, LBIAS)));
    }
    __syncthreads();

    // flush smem partials to the shared 64-bit totals (proven path)
    #pragma unroll
    for (int k = threadIdx.x; k < NPROP; k += 1024) {
        unsigned int v = s_acc[k];
        if (v) {
            unsigned long long g =
                ((unsigned long long)(v >> LCNT_SHIFT) << GCNT_SHIFT)
                + (unsigned long long)(v & 0x00FFFFFFu);
            atomicAdd(&g_acc[k], g);
        }
    }
}

// --- Kernel 2: epilogue, 8 blocks x 512 threads, 1 prop/thread ---------------
__global__ void __launch_bounds__(512, 1)
epilogue_kernel(const float* __restrict__ prop_freq,
                const int* __restrict__ bc_ptr,
                float* __restrict__ out,
                float n_tokens)
{
    const int k = blockIdx.x * 512 + threadIdx.x;   // 0..4095

    // prefetch everything independent of segacc
    const float pf = __ldg(&prop_freq[k]);
    const float bc = (float)__ldg(bc_ptr);

    const float EMA_DECAY = 0.99f;
    const float ONE_MINUS = 1.0f - 0.99f;
    const float MIN_FREQ  = 1e-5f;
    const float MAX_W     = 30.0f;
    const float WARMUP    = 1000.0f;
    const float SLOW      = 3000.0f;
    const float RAMPB     = 200.0f;

    const float ramp = fminf(1.0f, (bc - WARMUP) / RAMPB);
    const float frac = bc / SLOW;
    const bool  slow_blend = (bc <= SLOW);
    const bool  in_warmup  = (bc <= WARMUP);

    cudaGridDependencySynchronize();

    // smem-path totals
    unsigned long long v = g_acc[k];
    g_acc[k] = 0ULL;                                // reset for next replay
    unsigned long long cnt64   = v >> GCNT_SHIFT;
    unsigned long long units64 = v & (GONE - 1ULL);

    // merge the 148 CTA-private direct-RED rows (coalesced columns, L2-hot),
    // zeroing each cell in-pass (each cell touched by exactly one thread).
    #pragma unroll 4
    for (int c = 0; c < WORKERS; c++) {
        unsigned int p = g_part[c * NPROP + k];
        if (p) {
            g_part[c * NPROP + k] = 0u;
            cnt64   += (unsigned long long)(p >> LCNT_SHIFT);
            units64 += (unsigned long long)(p & 0x00FFFFFFu);
        }
    }

    float cnt = (float)cnt64;
    float sum = (float)units64 * GINV_SCALE;
    bool present = cnt64 != 0ULL;

    float mean = present ? (sum / fmaxf(cnt, 1.0f)) : 0.0f;

    // EMA frequency update
    float bfreq = cnt / (n_tokens + 1e-6f);
    float nf = pf * EMA_DECAY + (present ? ONE_MINUS * bfreq : 0.0f);
    out[2 + k] = nf;

    // inverse-frequency weight with warmup/ramp branches
    float fc  = fmaxf(nf, MIN_FREQ);
    float raw = rsqrtf(fc + 1e-6f);                 // 1/f^0.5
    raw = 1.0f + ramp * (raw - 1.0f);
    raw = fminf(MAX_W, raw);
    if (slow_blend) raw = raw * frac + (1.0f - frac);
    if (in_warmup)  raw = 1.0f;

    float w  = present ? raw : 0.0f;
    float mw = mean * w;

    // block tree reduction (512 threads = 16 warps), fixed order = deterministic
    const unsigned FULL = 0xFFFFFFFFu;
    unsigned long long tu = units64;
    #pragma unroll
    for (int off = 16; off > 0; off >>= 1) {
        mw += __shfl_down_sync(FULL, mw, off);
        w  += __shfl_down_sync(FULL, w,  off);
        tu += __shfl_down_sync(FULL, tu, off);
    }
    __shared__ float s_mw[16], s_w[16];
    __shared__ unsigned long long s_tu[16];
    int lane = threadIdx.x & 31, warp = threadIdx.x >> 5;
    if (lane == 0) { s_mw[warp] = mw; s_w[warp] = w; s_tu[warp] = tu; }
    __syncthreads();
    if (threadIdx.x == 0) {
        float bmw = 0.0f, bw = 0.0f;
        unsigned long long btu = 0ULL;
        #pragma unroll
        for (int j = 0; j < 16; j++) { bmw += s_mw[j]; bw += s_w[j]; btu += s_tu[j]; }
        // integer fixed-point atomics: exact + order-independent = deterministic
        atomicAdd(&g_scal[0], (unsigned long long)llrint((double)bmw * SCALE32));
        atomicAdd(&g_scal[1], (unsigned long long)llrint((double)bw  * SCALE32));
        atomicAdd(&g_scal[2], btu);
        __threadfence();
        if (atomicAdd(&g_ticket, 1u) == (unsigned)(gridDim.x - 1)) {
            __threadfence();   // acquire all blocks' g_scal contributions
            double dmw = (double)g_scal[0] / SCALE32;
            double dw  = (double)g_scal[1] / SCALE32;
            double dt  = (double)g_scal[2] * (1.0 / 65536.0);
            out[0] = (float)(dmw / (dw + 1e-6));        // stratified loss
            out[1] = (float)(dt / (double)n_tokens);    // unweighted mean loss
            g_scal[0] = 0ULL; g_scal[1] = 0ULL; g_scal[2] = 0ULL;
            g_ticket = 0;                               // reset for next replay
        }
    }
}

// ---------------------------------------------------------------------------
extern "C" void kernel_launch(void* const* d_in, const int* in_sizes, int n_in,
                              void* d_out, int out_size)
{
    const int*   ids    = (const int*)d_in[0];
    const float* losses = (const float*)d_in[1];
    const float* freq   = (const float*)d_in[2];
    const int*   bc     = (const int*)d_in[3];
    long long n = (long long)in_sizes[0];
    float* out = (float*)d_out;

    segacc_kernel<<<WORKERS, 1024>>>(ids, losses, n);

    cudaLaunchConfig_t cfg = {};
    cfg.gridDim  = dim3(NPROP / 512);
    cfg.blockDim = dim3(512);
    cfg.dynamicSmemBytes = 0;
    cfg.stream = 0;
    cudaLaunchAttribute attrs[1];
    attrs[0].id = cudaLaunchAttributeProgrammaticStreamSerialization;
    attrs[0].val.programmaticStreamSerializationAllowed = 1;
    cfg.attrs = attrs;
    cfg.numAttrs = 1;
    cudaLaunchKernelEx(&cfg, epilogue_kernel, freq, bc, out, (float)n);
}

// round 13
// speedup vs baseline: 2.0874x; 2.0874x over previous
#include <cuda_runtime.h>
#include <cstdint>

// ---------------------------------------------------------------------------
// MoE_72808285602017 — PropertyLossTracker fused segment reduction
//   inputs : property_ids (N int32), token_losses (N f32),
//            prop_freq (P f32), batch_counter (1 int32)
//   outputs: [stratified_loss, unweighted_loss, new_freq[P]]  (P+2 f32)
//
// R13: best-known config (R10, 31.46us: 148x1024 smem-ATOMS segacc + PDL
//      epilogue 8x512) with an 8-token inner iteration (two back-to-back
//      int4/float4 pairs) to raise front-batched MLP and cut loop overhead.
//      Hybrid-routing and fusion variants all measured worse; reverted.
// ---------------------------------------------------------------------------

#define NPROP 4096
#define NBLOCKS 148

// Local 32-bit cell: (count << 24) + round(loss * 2^16) via one FFMA+F2I
// per-block tokens ~113k -> per-cell expected ~27.6 counts (cap 255), safe.
#define LSCALE 65536.0f
#define LBIAS  16777216.0f            // 2^24 == one local count unit
#define LCNT_SHIFT 24

// Global 64-bit cell: (count << 40) + sum_units16
#define GCNT_SHIFT 40
#define GINV_SCALE (1.0f / 65536.0f)
#define GONE (1ULL << GCNT_SHIFT)

#define SCALE32 4294967296.0          // 2^32 fixed point for scalar merge

__device__ unsigned long long g_acc[NPROP];   // zeroed at load; epilogue re-zeroes
__device__ unsigned long long g_scal[3];      // {mw, w, t_units16}; last block resets
__device__ unsigned int       g_ticket;       // epilogue block ticket

// --- Kernel 1: token accumulation --------------------------------------------
__global__ void __launch_bounds__(1024, 1)
segacc_kernel(const int* __restrict__ ids,
              const float* __restrict__ losses,
              long long n)
{
    // PDL: allow the dependent epilogue to launch early (free; worth ~0.4us).
    cudaTriggerProgrammaticLaunchCompletion();

    __shared__ unsigned int s_acc[NPROP];
    #pragma unroll
    for (int i = threadIdx.x; i < NPROP; i += 1024) s_acc[i] = 0u;
    __syncthreads();

    const long long n4 = n >> 2;                 // N is a multiple of 4
    const int4*   id4 = (const int4*)ids;
    const float4* ls4 = (const float4*)losses;
    const long long stride  = (long long)gridDim.x * 1024;
    const long long stride2 = stride * 2;

    long long i = (long long)blockIdx.x * 1024 + threadIdx.x;

    // 8 tokens per iteration: two int4+float4 pairs issued back-to-back so
    // all four wide loads are in flight before any atomic consumes them.
    for (; i + stride < n4; i += stride2) {
        int4   ida = id4[i];
        float4 lsa = ls4[i];
        int4   idb = id4[i + stride];
        float4 lsb = ls4[i + stride];
        atomicAdd(&s_acc[ida.x], __float2uint_rn(fmaf(lsa.x, LSCALE, LBIAS)));
        atomicAdd(&s_acc[ida.y], __float2uint_rn(fmaf(lsa.y, LSCALE, LBIAS)));
        atomicAdd(&s_acc[ida.z], __float2uint_rn(fmaf(lsa.z, LSCALE, LBIAS)));
        atomicAdd(&s_acc[ida.w], __float2uint_rn(fmaf(lsa.w, LSCALE, LBIAS)));
        atomicAdd(&s_acc[idb.x], __float2uint_rn(fmaf(lsb.x, LSCALE, LBIAS)));
        atomicAdd(&s_acc[idb.y], __float2uint_rn(fmaf(lsb.y, LSCALE, LBIAS)));
        atomicAdd(&s_acc[idb.z], __float2uint_rn(fmaf(lsb.z, LSCALE, LBIAS)));
        atomicAdd(&s_acc[idb.w], __float2uint_rn(fmaf(lsb.w, LSCALE, LBIAS)));
    }
    // leftover single vec4 iteration
    for (; i < n4; i += stride) {
        int4   id = id4[i];
        float4 ls = ls4[i];
        atomicAdd(&s_acc[id.x], __float2uint_rn(fmaf(ls.x, LSCALE, LBIAS)));
        atomicAdd(&s_acc[id.y], __float2uint_rn(fmaf(ls.y, LSCALE, LBIAS)));
        atomicAdd(&s_acc[id.z], __float2uint_rn(fmaf(ls.z, LSCALE, LBIAS)));
        atomicAdd(&s_acc[id.w], __float2uint_rn(fmaf(ls.w, LSCALE, LBIAS)));
    }
    // scalar tail (defensive; N % 4 == 0 here)
    for (long long t = (n4 << 2) + (long long)blockIdx.x * 1024 + threadIdx.x;
         t < n; t += stride) {
        atomicAdd(&s_acc[ids[t]], __float2uint_rn(fmaf(losses[t], LSCALE, LBIAS)));
    }
    __syncthreads();

    // flush block partials to global (repacked to 64-bit layout)
    #pragma unroll
    for (int k = threadIdx.x; k < NPROP; k += 1024) {
        unsigned int v = s_acc[k];
        if (v) {
            unsigned long long g =
                ((unsigned long long)(v >> LCNT_SHIFT) << GCNT_SHIFT)
                + (unsigned long long)(v & 0x00FFFFFFu);
            atomicAdd(&g_acc[k], g);
        }
    }
}

// --- Kernel 2: PDL epilogue, 8 blocks x 512 threads, 1 prop/thread -----------
__global__ void __launch_bounds__(512, 1)
epilogue_kernel(const float* __restrict__ prop_freq,
                const int* __restrict__ bc_ptr,
                float* __restrict__ out,
                float n_tokens)
{
    const int k = blockIdx.x * 512 + threadIdx.x;   // 0..4095

    // ---- prefetch everything independent of segacc ------------------------
    const float pf = __ldg(&prop_freq[k]);
    const float bc = (float)__ldg(bc_ptr);

    const float EMA_DECAY = 0.99f;
    const float ONE_MINUS = 1.0f - 0.99f;
    const float MIN_FREQ  = 1e-5f;
    const float MAX_W     = 30.0f;
    const float WARMUP    = 1000.0f;
    const float SLOW      = 3000.0f;
    const float RAMPB     = 200.0f;

    const float ramp = fminf(1.0f, (bc - WARMUP) / RAMPB);
    const float frac = bc / SLOW;
    const bool  slow_blend = (bc <= SLOW);
    const bool  in_warmup  = (bc <= WARMUP);

    // ---- wait for segacc's grid completion + memory visibility ------------
    cudaGridDependencySynchronize();

    unsigned long long v = g_acc[k];
    g_acc[k] = 0ULL;                                // reset scratch for next replay

    float cnt = (float)(v >> GCNT_SHIFT);
    unsigned long long units = v & (GONE - 1ULL);
    float sum = (float)units * GINV_SCALE;
    bool present = cnt > 0.0f;

    float mean = present ? (sum / fmaxf(cnt, 1.0f)) : 0.0f;

    // EMA frequency update
    float bfreq = cnt / (n_tokens + 1e-6f);
    float nf = pf * EMA_DECAY + (present ? ONE_MINUS * bfreq : 0.0f);
    out[2 + k] = nf;

    // inverse-frequency weight with warmup/ramp branches
    float fc  = fmaxf(nf, MIN_FREQ);
    float raw = rsqrtf(fc + 1e-6f);                 // 1/f^0.5
    raw = 1.0f + ramp * (raw - 1.0f);
    raw = fminf(MAX_W, raw);
    if (slow_blend) raw = raw * frac + (1.0f - frac);
    if (in_warmup)  raw = 1.0f;

    float w  = present ? raw : 0.0f;
    float mw = mean * w;

    // block tree reduction (512 threads = 16 warps), fixed order = deterministic
    const unsigned FULL = 0xFFFFFFFFu;
    unsigned long long tu = units;
    #pragma unroll
    for (int off = 16; off > 0; off >>= 1) {
        mw += __shfl_down_sync(FULL, mw, off);
        w  += __shfl_down_sync(FULL, w,  off);
        tu += __shfl_down_sync(FULL, tu, off);
    }
    __shared__ float s_mw[16], s_w[16];
    __shared__ unsigned long long s_tu[16];
    int lane = threadIdx.x & 31, warp = threadIdx.x >> 5;
    if (lane == 0) { s_mw[warp] = mw; s_w[warp] = w; s_tu[warp] = tu; }
    __syncthreads();
    if (threadIdx.x == 0) {
        float bmw = 0.0f, bw = 0.0f;
        unsigned long long btu = 0ULL;
        #pragma unroll
        for (int j = 0; j < 16; j++) { bmw += s_mw[j]; bw += s_w[j]; btu += s_tu[j]; }
        // integer fixed-point atomics: exact + order-independent = deterministic
        atomicAdd(&g_scal[0], (unsigned long long)llrint((double)bmw * SCALE32));
        atomicAdd(&g_scal[1], (unsigned long long)llrint((double)bw  * SCALE32));
        atomicAdd(&g_scal[2], btu);
        __threadfence();
        if (atomicAdd(&g_ticket, 1u) == (unsigned)(gridDim.x - 1)) {
            __threadfence();   // acquire all blocks' g_scal contributions
            double dmw = (double)g_scal[0] / SCALE32;
            double dw  = (double)g_scal[1] / SCALE32;
            double dt  = (double)g_scal[2] * (1.0 / 65536.0);
            out[0] = (float)(dmw / (dw + 1e-6));        // stratified loss
            out[1] = (float)(dt / (double)n_tokens);    // unweighted mean loss
            g_scal[0] = 0ULL; g_scal[1] = 0ULL; g_scal[2] = 0ULL;
            g_ticket = 0;                               // reset for next replay
        }
    }
}

// ---------------------------------------------------------------------------
extern "C" void kernel_launch(void* const* d_in, const int* in_sizes, int n_in,
                              void* d_out, int out_size)
{
    const int*   ids    = (const int*)d_in[0];
    const float* losses = (const float*)d_in[1];
    const float* freq   = (const float*)d_in[2];
    const int*   bc     = (const int*)d_in[3];
    long long n = (long long)in_sizes[0];
    float* out = (float*)d_out;

    segacc_kernel<<<NBLOCKS, 1024>>>(ids, losses, n);

    cudaLaunchConfig_t cfg = {};
    cfg.gridDim  = dim3(NPROP / 512);
    cfg.blockDim = dim3(512);
    cfg.dynamicSmemBytes = 0;
    cfg.stream = 0;
    cudaLaunchAttribute attrs[1];
    attrs[0].id = cudaLaunchAttributeProgrammaticStreamSerialization;
    attrs[0].val.programmaticStreamSerializationAllowed = 1;
    cfg.attrs = attrs;
    cfg.numAttrs = 1;
    cudaLaunchKernelEx(&cfg, epilogue_kernel, freq, bc, out, (float)n);
}

// round 14
// speedup vs baseline: 2.0895x; 1.0010x over previous
#include <cuda_runtime.h>
#include <cstdint>

// ---------------------------------------------------------------------------
// MoE_72808285602017 — PropertyLossTracker fused segment reduction
//   inputs : property_ids (N int32), token_losses (N f32),
//            prop_freq (P f32), batch_counter (1 int32)
//   outputs: [stratified_loss, unweighted_loss, new_freq[P]]  (P+2 f32)
//
// R14: proven segacc (148x1024 smem-ATOMS, at the ATOMS hardware rate) +
//      minimal-latency epilogue: ONE block, 4 contiguous props/thread,
//      coalesced vector loads, block-local reduction only. Removes g_scal
//      atomics, the ticket, and both threadfences (a 4-deep global round-trip
//      chain) from the critical path.
// ---------------------------------------------------------------------------

#define NPROP 4096
#define NBLOCKS 148

// Local 32-bit cell: (count << 24) + round(loss * 2^16) via one FFMA+F2I
#define LSCALE 65536.0f
#define LBIAS  16777216.0f            // 2^24 == one local count unit
#define LCNT_SHIFT 24

// Global 64-bit cell: (count << 40) + sum_units16
#define GCNT_SHIFT 40
#define GINV_SCALE (1.0f / 65536.0f)
#define GONE (1ULL << GCNT_SHIFT)

__device__ unsigned long long g_acc[NPROP];   // zeroed at load; epilogue re-zeroes

// --- Kernel 1: token accumulation (proven, at ATOMS floor) -------------------
__global__ void __launch_bounds__(1024, 1)
segacc_kernel(const int* __restrict__ ids,
              const float* __restrict__ losses,
              long long n)
{
    // PDL: allow the dependent epilogue to launch early (free).
    cudaTriggerProgrammaticLaunchCompletion();

    __shared__ unsigned int s_acc[NPROP];
    #pragma unroll
    for (int i = threadIdx.x; i < NPROP; i += 1024) s_acc[i] = 0u;
    __syncthreads();

    const long long n4 = n >> 2;                 // N is a multiple of 4
    const int4*   id4 = (const int4*)ids;
    const float4* ls4 = (const float4*)losses;
    const long long stride = (long long)gridDim.x * 1024;

    long long i = (long long)blockIdx.x * 1024 + threadIdx.x;
    #pragma unroll 2
    for (; i < n4; i += stride) {
        int4   id = id4[i];
        float4 ls = ls4[i];
        atomicAdd(&s_acc[id.x], __float2uint_rn(fmaf(ls.x, LSCALE, LBIAS)));
        atomicAdd(&s_acc[id.y], __float2uint_rn(fmaf(ls.y, LSCALE, LBIAS)));
        atomicAdd(&s_acc[id.z], __float2uint_rn(fmaf(ls.z, LSCALE, LBIAS)));
        atomicAdd(&s_acc[id.w], __float2uint_rn(fmaf(ls.w, LSCALE, LBIAS)));
    }
    // scalar tail (defensive; N % 4 == 0 here)
    for (long long t = (n4 << 2) + (long long)blockIdx.x * 1024 + threadIdx.x;
         t < n; t += stride) {
        atomicAdd(&s_acc[ids[t]], __float2uint_rn(fmaf(losses[t], LSCALE, LBIAS)));
    }
    __syncthreads();

    // flush block partials to global (repacked to 64-bit layout)
    #pragma unroll
    for (int k = threadIdx.x; k < NPROP; k += 1024) {
        unsigned int v = s_acc[k];
        if (v) {
            unsigned long long g =
                ((unsigned long long)(v >> LCNT_SHIFT) << GCNT_SHIFT)
                + (unsigned long long)(v & 0x00FFFFFFu);
            atomicAdd(&g_acc[k], g);
        }
    }
}

// --- Kernel 2: single-block epilogue, 4 contiguous props/thread --------------
__global__ void __launch_bounds__(1024, 1)
epilogue_kernel(const float* __restrict__ prop_freq,
                const int* __restrict__ bc_ptr,
                float* __restrict__ out,
                float n_tokens)
{
    const int tid = threadIdx.x;
    const int k0  = tid * 4;                         // props k0..k0+3

    // ---- prefetch everything independent of segacc ------------------------
    const float4 pf4 = *(const float4*)&prop_freq[k0];   // 16B-aligned input
    const float  bc  = (float)__ldg(bc_ptr);

    const float EMA_DECAY = 0.99f;
    const float ONE_MINUS = 1.0f - 0.99f;
    const float MIN_FREQ  = 1e-5f;
    const float MAX_W     = 30.0f;
    const float WARMUP    = 1000.0f;
    const float SLOW      = 3000.0f;
    const float RAMPB     = 200.0f;

    const float ramp = fminf(1.0f, (bc - WARMUP) / RAMPB);
    const float frac = bc / SLOW;
    const bool  slow_blend = (bc <= SLOW);
    const bool  in_warmup  = (bc <= WARMUP);

    // ---- wait for segacc's grid completion + memory visibility ------------
    cudaGridDependencySynchronize();

    // 4 independent 64-bit loads in flight (MLP=4), then reset scratch
    unsigned long long v0 = g_acc[k0 + 0];
    unsigned long long v1 = g_acc[k0 + 1];
    unsigned long long v2 = g_acc[k0 + 2];
    unsigned long long v3 = g_acc[k0 + 3];
    g_acc[k0 + 0] = 0ULL; g_acc[k0 + 1] = 0ULL;
    g_acc[k0 + 2] = 0ULL; g_acc[k0 + 3] = 0ULL;

    float s_mw = 0.0f, s_w = 0.0f;
    unsigned long long s_tu = 0ULL;
    float nf_out[4];
    const float pf[4] = {pf4.x, pf4.y, pf4.z, pf4.w};
    unsigned long long vv[4] = {v0, v1, v2, v3};

    #pragma unroll
    for (int j = 0; j < 4; j++) {
        unsigned long long v = vv[j];
        float cnt = (float)(v >> GCNT_SHIFT);
        unsigned long long units = v & (GONE - 1ULL);
        float sum = (float)units * GINV_SCALE;
        bool present = v != 0ULL ? (cnt > 0.0f) : false;

        float mean = present ? (sum / fmaxf(cnt, 1.0f)) : 0.0f;

        // EMA frequency update
        float bfreq = cnt / (n_tokens + 1e-6f);
        float nf = pf[j] * EMA_DECAY + (present ? ONE_MINUS * bfreq : 0.0f);
        nf_out[j] = nf;

        // inverse-frequency weight with warmup/ramp branches
        float fc  = fmaxf(nf, MIN_FREQ);
        float raw = rsqrtf(fc + 1e-6f);              // 1/f^0.5
        raw = 1.0f + ramp * (raw - 1.0f);
        raw = fminf(MAX_W, raw);
        if (slow_blend) raw = raw * frac + (1.0f - frac);
        if (in_warmup)  raw = 1.0f;

        float w = present ? raw : 0.0f;
        s_w  += w;
        s_mw += mean * w;
        s_tu += units;
    }

    // out + 2 is 8-byte aligned: two float2 stores
    *(float2*)&out[2 + k0]     = make_float2(nf_out[0], nf_out[1]);
    *(float2*)&out[2 + k0 + 2] = make_float2(nf_out[2], nf_out[3]);

    // block tree reduction (1024 threads = 32 warps), fixed order = deterministic
    const unsigned FULL = 0xFFFFFFFFu;
    #pragma unroll
    for (int off = 16; off > 0; off >>= 1) {
        s_mw += __shfl_down_sync(FULL, s_mw, off);
        s_w  += __shfl_down_sync(FULL, s_w,  off);
        s_tu += __shfl_down_sync(FULL, s_tu, off);
    }
    __shared__ float r_mw[32], r_w[32];
    __shared__ unsigned long long r_tu[32];
    int lane = tid & 31, warp = tid >> 5;
    if (lane == 0) { r_mw[warp] = s_mw; r_w[warp] = s_w; r_tu[warp] = s_tu; }
    __syncthreads();
    if (warp == 0) {
        s_mw = r_mw[lane]; s_w = r_w[lane]; s_tu = r_tu[lane];
        #pragma unroll
        for (int off = 16; off > 0; off >>= 1) {
            s_mw += __shfl_down_sync(FULL, s_mw, off);
            s_w  += __shfl_down_sync(FULL, s_w,  off);
            s_tu += __shfl_down_sync(FULL, s_tu, off);
        }
        if (lane == 0) {
            out[0] = s_mw / (s_w + 1e-6f);                       // stratified
            out[1] = (float)((double)s_tu * (1.0 / 65536.0)
                             / (double)n_tokens);                // unweighted
        }
    }
}

// ---------------------------------------------------------------------------
extern "C" void kernel_launch(void* const* d_in, const int* in_sizes, int n_in,
                              void* d_out, int out_size)
{
    const int*   ids    = (const int*)d_in[0];
    const float* losses = (const float*)d_in[1];
    const float* freq   = (const float*)d_in[2];
    const int*   bc     = (const int*)d_in[3];
    long long n = (long long)in_sizes[0];
    float* out = (float*)d_out;

    segacc_kernel<<<NBLOCKS, 1024>>>(ids, losses, n);

    cudaLaunchConfig_t cfg = {};
    cfg.gridDim  = dim3(1);
    cfg.blockDim = dim3(1024);
    cfg.dynamicSmemBytes = 0;
    cfg.stream = 0;
    cudaLaunchAttribute attrs[1];
    attrs[0].id = cudaLaunchAttributeProgrammaticStreamSerialization;
    attrs[0].val.programmaticStreamSerializationAllowed = 1;
    cfg.attrs = attrs;
    cfg.numAttrs = 1;
    cudaLaunchKernelEx(&cfg, epilogue_kernel, freq, bc, out, (float)n);
}

// round 15
// speedup vs baseline: 2.1024x; 1.0061x over previous
#include <cuda_runtime.h>
#include <cstdint>

// ---------------------------------------------------------------------------
// MoE_72808285602017 — PropertyLossTracker fused segment reduction
//   inputs : property_ids (N int32), token_losses (N f32),
//            prop_freq (P f32), batch_counter (1 int32)
//   outputs: [stratified_loss, unweighted_loss, new_freq[P]]  (P+2 f32)
//
// R15: ONE kernel, grid = exactly 148 (1 CTA/SM, perfectly balanced — R9's
//      fusion failed from grid=152 placement stragglers; R3's from 296-block
//      spread + heavy tail). Workers run the proven segacc body; after flush,
//      fence+ticket elects the LAST block to run the lean R14 epilogue inline
//      (4 props/thread, L2-hot __ldcg, block-local reduction). Removes the
//      ~8.3us second-graph-node cost that pinned R5-R14 at 31.5us.
// ---------------------------------------------------------------------------

#define NPROP 4096
#define NBLOCKS 148

// Local 32-bit cell: (count << 24) + round(loss * 2^16) via one FFMA+F2I
// per-block tokens ~113k -> ~27.6 counts/cell expected (cap 255), safe.
#define LSCALE 65536.0f
#define LBIAS  16777216.0f            // 2^24 == one local count unit
#define LCNT_SHIFT 24

// Global 64-bit cell: (count << 40) + sum_units16
#define GCNT_SHIFT 40
#define GINV_SCALE (1.0f / 65536.0f)
#define GONE (1ULL << GCNT_SHIFT)

__device__ unsigned long long g_acc[NPROP];   // zeroed at load; last block re-zeroes
__device__ unsigned int       g_ticket;       // zeroed at load; last block re-zeroes

__global__ void __launch_bounds__(1024, 1)
fused_kernel(const int* __restrict__ ids,
             const float* __restrict__ losses,
             const float* __restrict__ prop_freq,
             const int* __restrict__ bc_ptr,
             float* __restrict__ out,
             long long n)
{
    const int tid = threadIdx.x;

    // =================== segacc body (proven, at pipe floor) ===============
    __shared__ unsigned int s_acc[NPROP];
    #pragma unroll
    for (int i = tid; i < NPROP; i += 1024) s_acc[i] = 0u;
    __syncthreads();

    const long long n4 = n >> 2;                 // N is a multiple of 4
    const int4*   id4 = (const int4*)ids;
    const float4* ls4 = (const float4*)losses;
    const long long stride = (long long)NBLOCKS * 1024;

    long long i = (long long)blockIdx.x * 1024 + tid;
    #pragma unroll 2
    for (; i < n4; i += stride) {
        int4   id = id4[i];
        float4 ls = ls4[i];
        atomicAdd(&s_acc[id.x], __float2uint_rn(fmaf(ls.x, LSCALE, LBIAS)));
        atomicAdd(&s_acc[id.y], __float2uint_rn(fmaf(ls.y, LSCALE, LBIAS)));
        atomicAdd(&s_acc[id.z], __float2uint_rn(fmaf(ls.z, LSCALE, LBIAS)));
        atomicAdd(&s_acc[id.w], __float2uint_rn(fmaf(ls.w, LSCALE, LBIAS)));
    }
    // scalar tail (defensive; N % 4 == 0 here)
    for (long long t = (n4 << 2) + (long long)blockIdx.x * 1024 + tid;
         t < n; t += stride) {
        atomicAdd(&s_acc[ids[t]], __float2uint_rn(fmaf(losses[t], LSCALE, LBIAS)));
    }
    __syncthreads();

    // flush block partials to global (repacked to 64-bit layout)
    #pragma unroll
    for (int k = tid; k < NPROP; k += 1024) {
        unsigned int v = s_acc[k];
        if (v) {
            unsigned long long g =
                ((unsigned long long)(v >> LCNT_SHIFT) << GCNT_SHIFT)
                + (unsigned long long)(v & 0x00FFFFFFu);
            atomicAdd(&g_acc[k], g);
        }
    }

    // =================== prefetch epilogue inputs (all blocks; L2-cheap) ===
    const int k0 = tid * 4;
    const float4 pf4 = *(const float4*)&prop_freq[k0];
    const float  bc  = (float)__ldg(bc_ptr);

    // =================== fence + ticket: elect last block ==================
    __shared__ bool s_last;
    __threadfence();                 // make this block's g_acc atomics visible
    __syncthreads();                 // all threads' fences done
    if (tid == 0)
        s_last = (atomicAdd(&g_ticket, 1u) == (unsigned)(NBLOCKS - 1));
    __syncthreads();
    if (!s_last) return;
    __threadfence();                 // acquire: all blocks' atomics visible

    // =================== lean epilogue (last block only) ===================
    const float n_tokens = (float)n;
    const float EMA_DECAY = 0.99f;
    const float ONE_MINUS = 1.0f - 0.99f;
    const float MIN_FREQ  = 1e-5f;
    const float MAX_W     = 30.0f;
    const float WARMUP    = 1000.0f;
    const float SLOW      = 3000.0f;
    const float RAMPB     = 200.0f;

    const float ramp = fminf(1.0f, (bc - WARMUP) / RAMPB);
    const float frac = bc / SLOW;
    const bool  slow_blend = (bc <= SLOW);
    const bool  in_warmup  = (bc <= WARMUP);

    // 4 independent L2-hot loads in flight, then reset scratch
    unsigned long long v0 = __ldcg(&g_acc[k0 + 0]);
    unsigned long long v1 = __ldcg(&g_acc[k0 + 1]);
    unsigned long long v2 = __ldcg(&g_acc[k0 + 2]);
    unsigned long long v3 = __ldcg(&g_acc[k0 + 3]);
    g_acc[k0 + 0] = 0ULL; g_acc[k0 + 1] = 0ULL;
    g_acc[k0 + 2] = 0ULL; g_acc[k0 + 3] = 0ULL;

    float s_mw = 0.0f, s_w = 0.0f;
    unsigned long long s_tu = 0ULL;
    float nf_out[4];
    const float pf[4] = {pf4.x, pf4.y, pf4.z, pf4.w};
    unsigned long long vv[4] = {v0, v1, v2, v3};

    #pragma unroll
    for (int j = 0; j < 4; j++) {
        unsigned long long v = vv[j];
        float cnt = (float)(v >> GCNT_SHIFT);
        unsigned long long units = v & (GONE - 1ULL);
        float sum = (float)units * GINV_SCALE;
        bool present = cnt > 0.0f;

        float mean = present ? (sum / fmaxf(cnt, 1.0f)) : 0.0f;

        // EMA frequency update
        float bfreq = cnt / (n_tokens + 1e-6f);
        float nf = pf[j] * EMA_DECAY + (present ? ONE_MINUS * bfreq : 0.0f);
        nf_out[j] = nf;

        // inverse-frequency weight with warmup/ramp branches
        float fc  = fmaxf(nf, MIN_FREQ);
        float raw = rsqrtf(fc + 1e-6f);              // 1/f^0.5
        raw = 1.0f + ramp * (raw - 1.0f);
        raw = fminf(MAX_W, raw);
        if (slow_blend) raw = raw * frac + (1.0f - frac);
        if (in_warmup)  raw = 1.0f;

        float w = present ? raw : 0.0f;
        s_w  += w;
        s_mw += mean * w;
        s_tu += units;
    }

    // out + 2 is 8-byte aligned: two float2 stores
    *(float2*)&out[2 + k0]     = make_float2(nf_out[0], nf_out[1]);
    *(float2*)&out[2 + k0 + 2] = make_float2(nf_out[2], nf_out[3]);

    // block tree reduction (32 warps), fixed order = deterministic;
    // reuse s_acc as scratch (safe after syncthreads above)
    float* r_mw = (float*)&s_acc[0];
    float* r_w  = (float*)&s_acc[32];
    unsigned long long* r_tu = (unsigned long long*)&s_acc[64];
    const unsigned FULL = 0xFFFFFFFFu;
    #pragma unroll
    for (int off = 16; off > 0; off >>= 1) {
        s_mw += __shfl_down_sync(FULL, s_mw, off);
        s_w  += __shfl_down_sync(FULL, s_w,  off);
        s_tu += __shfl_down_sync(FULL, s_tu, off);
    }
    int lane = tid & 31, warp = tid >> 5;
    if (lane == 0) { r_mw[warp] = s_mw; r_w[warp] = s_w; r_tu[warp] = s_tu; }
    __syncthreads();
    if (warp == 0) {
        s_mw = r_mw[lane]; s_w = r_w[lane]; s_tu = r_tu[lane];
        #pragma unroll
        for (int off = 16; off > 0; off >>= 1) {
            s_mw += __shfl_down_sync(FULL, s_mw, off);
            s_w  += __shfl_down_sync(FULL, s_w,  off);
            s_tu += __shfl_down_sync(FULL, s_tu, off);
        }
        if (lane == 0) {
            out[0] = s_mw / (s_w + 1e-6f);                        // stratified
            out[1] = (float)((double)s_tu * (1.0 / 65536.0)
                             / (double)n_tokens);                 // unweighted
            g_ticket = 0u;                            // reset for next replay
        }
    }
}

// ---------------------------------------------------------------------------
extern "C" void kernel_launch(void* const* d_in, const int* in_sizes, int n_in,
                              void* d_out, int out_size)
{
    const int*   ids    = (const int*)d_in[0];
    const float* losses = (const float*)d_in[1];
    const float* freq   = (const float*)d_in[2];
    const int*   bc     = (const int*)d_in[3];
    long long n = (long long)in_sizes[0];
    float* out = (float*)d_out;

    fused_kernel<<<NBLOCKS, 1024>>>(ids, losses, freq, bc, out, n);
}